// round 1
// baseline (speedup 1.0000x reference)
#include <cuda_runtime.h>
#include <math.h>
#include <float.h>

#define NN 50000
#define EE 800000

// ---------------- static scratch (no allocations allowed) ----------------
__device__ float g_F[NN * 256];      // [fni(64) | fnj(64) | ft(128)] per node
__device__ float g_h[NN * 128];      // layer activations
__device__ float g_Wcat[128 * 256];  // packed [Wni|Wnj|Wn]
__device__ int   g_rowptr[NN + 1];
__device__ int   g_cursor[NN];       // counts, then scatter cursors
__device__ int   g_perm[EE];         // edge ids grouped by dst

// ---------------- CSR build ----------------
__global__ void zero_k(int* p, int n) {
    int i = blockIdx.x * blockDim.x + threadIdx.x;
    if (i < n) p[i] = 0;
}

__global__ void count_k(const int* __restrict__ dst, int* counts, int e) {
    int i = blockIdx.x * blockDim.x + threadIdx.x;
    if (i < e) atomicAdd(&counts[dst[i]], 1);
}

__global__ void scan_k(const int* __restrict__ counts, int* __restrict__ rowptr, int n) {
    __shared__ int sh[1024];
    __shared__ int base_s;
    int tid = threadIdx.x;
    if (tid == 0) { rowptr[0] = 0; base_s = 0; }
    __syncthreads();
    for (int start = 0; start < n; start += 1024) {
        int i = start + tid;
        int v = (i < n) ? counts[i] : 0;
        sh[tid] = v;
        __syncthreads();
        for (int o = 1; o < 1024; o <<= 1) {
            int t = (tid >= o) ? sh[tid - o] : 0;
            __syncthreads();
            sh[tid] += t;
            __syncthreads();
        }
        if (i < n) rowptr[i + 1] = base_s + sh[tid];
        __syncthreads();
        if (tid == 0) base_s += sh[1023];
        __syncthreads();
    }
}

__global__ void copy_k(const int* __restrict__ a, int* __restrict__ b, int n) {
    int i = blockIdx.x * blockDim.x + threadIdx.x;
    if (i < n) b[i] = a[i];
}

__global__ void scatter_k(const int* __restrict__ dst, int* cursor, int* __restrict__ perm, int e) {
    int i = blockIdx.x * blockDim.x + threadIdx.x;
    if (i < e) {
        int p = atomicAdd(&cursor[dst[i]], 1);
        perm[p] = i;
    }
}

// ---------------- weight pack: Wcat = [Wni | Wnj | Wn] ----------------
__global__ void pack_k(const float* __restrict__ Wni, const float* __restrict__ Wnj,
                       const float* __restrict__ Wn, float* __restrict__ Wcat) {
    int idx = blockIdx.x * blockDim.x + threadIdx.x;  // 128*256
    if (idx >= 128 * 256) return;
    int k = idx >> 8, c = idx & 255;
    float v;
    if (c < 64)       v = Wni[k * 64 + c];
    else if (c < 128) v = Wnj[k * 64 + (c - 64)];
    else              v = Wn[k * 128 + (c - 128)];
    Wcat[idx] = v;
}

// ---------------- SGEMM: C(n x cn) = A(n x 128) @ B(128 x cn) ----------------
// 128x128 block tile, BK=8, 256 threads, 8x8 per-thread microtile.
#define BM 128
#define BN 128
#define BKK 8

__global__ __launch_bounds__(256) void sgemm_k(
    const float* __restrict__ A, const float* __restrict__ B,
    float* __restrict__ C, int n, int cn,
    const float* __restrict__ bias, int doRelu)
{
    __shared__ float As[BKK][BM];
    __shared__ float Bs[BKK][BN];
    int tid = threadIdx.x;
    int rowBase = blockIdx.y * BM;
    int colBase = blockIdx.x * BN;

    int innerRowA = tid >> 1;            // 0..127
    int innerColA = (tid & 1) * 4;       // 0 or 4
    int innerRowB = tid >> 5;            // 0..7
    int innerColB = (tid & 31) * 4;      // 0..124

    int tr = tid >> 4;   // 0..15 : rows tr*8..
    int tc = tid & 15;   // 0..15 : cols tc*8..

    float acc[8][8];
#pragma unroll
    for (int i = 0; i < 8; i++)
#pragma unroll
        for (int j = 0; j < 8; j++) acc[i][j] = 0.f;

    bool aValid = (rowBase + innerRowA) < n;
    const float* Aptr = A + (size_t)(rowBase + innerRowA) * 128 + innerColA;
    const float* Bptr = B + (size_t)innerRowB * cn + colBase + innerColB;

    for (int kk = 0; kk < 128; kk += BKK) {
        float4 av = aValid ? *(const float4*)(Aptr + kk) : make_float4(0.f, 0.f, 0.f, 0.f);
        As[innerColA + 0][innerRowA] = av.x;
        As[innerColA + 1][innerRowA] = av.y;
        As[innerColA + 2][innerRowA] = av.z;
        As[innerColA + 3][innerRowA] = av.w;
        float4 bv = *(const float4*)(Bptr + (size_t)kk * cn);
        *(float4*)&Bs[innerRowB][innerColB] = bv;
        __syncthreads();
#pragma unroll
        for (int k = 0; k < BKK; k++) {
            float regM[8], regN[8];
            *(float4*)&regM[0] = *(float4*)&As[k][tr * 8];
            *(float4*)&regM[4] = *(float4*)&As[k][tr * 8 + 4];
            *(float4*)&regN[0] = *(float4*)&Bs[k][tc * 8];
            *(float4*)&regN[4] = *(float4*)&Bs[k][tc * 8 + 4];
#pragma unroll
            for (int i = 0; i < 8; i++)
#pragma unroll
                for (int j = 0; j < 8; j++)
                    acc[i][j] = fmaf(regM[i], regN[j], acc[i][j]);
        }
        __syncthreads();
    }

#pragma unroll
    for (int i = 0; i < 8; i++) {
        int row = rowBase + tr * 8 + i;
        if (row >= n) continue;
#pragma unroll
        for (int j = 0; j < 8; j += 4) {
            int col = colBase + tc * 8 + j;
            float4 v = make_float4(acc[i][j], acc[i][j + 1], acc[i][j + 2], acc[i][j + 3]);
            if (bias) {
                v.x += bias[col]; v.y += bias[col + 1]; v.z += bias[col + 2]; v.w += bias[col + 3];
            }
            if (doRelu) {
                v.x = fmaxf(v.x, 0.f); v.y = fmaxf(v.y, 0.f);
                v.z = fmaxf(v.z, 0.f); v.w = fmaxf(v.w, 0.f);
            }
            *(float4*)&C[(size_t)row * cn + col] = v;
        }
    }
}

// ---------------- fused EGAT edge phase: one warp per dst node ----------------
// F: [fni(64)|fnj(64)|ft(128)] per node. Online softmax over incoming edges.
// Output: out[v, h*32+lane] = relu( sum_e a[e,h]*ft[src[e], h*32+lane] )
__global__ __launch_bounds__(256) void egat_k(
    const float* __restrict__ F, const float* __restrict__ ew,
    const int* __restrict__ rowptr, const int* __restrict__ perm,
    const int* __restrict__ src, const float* __restrict__ Wfij,
    const float* __restrict__ attn, const float* __restrict__ bias,
    float* __restrict__ out, int n)
{
    int warpId = (blockIdx.x * blockDim.x + threadIdx.x) >> 5;
    int lane = threadIdx.x & 31;
    if (warpId >= n) return;
    int v = warpId;
    int c0 = lane, c1 = lane + 32;

    // per-lane Wfij columns in registers (16x2 floats)
    float Wc0[16], Wc1[16];
#pragma unroll
    for (int j = 0; j < 16; j++) {
        Wc0[j] = Wfij[j * 64 + c0];
        Wc1[j] = Wfij[j * 64 + c1];
    }
    float a0 = attn[c0], a1 = attn[c1];
    float base0 = F[(size_t)v * 256 + 64 + c0] + bias[c0];  // f_nj[dst] + b
    float base1 = F[(size_t)v * 256 + 64 + c1] + bias[c1];

    int beg = rowptr[v], end = rowptr[v + 1];

    float m0 = -FLT_MAX, m1 = -FLT_MAX, m2 = -FLT_MAX, m3 = -FLT_MAX;
    float s0 = 0.f, s1 = 0.f, s2 = 0.f, s3 = 0.f;
    float A0 = 0.f, A1 = 0.f, A2 = 0.f, A3 = 0.f;

    for (int ei = beg; ei < end; ei++) {
        int e = perm[ei];
        int u = src[e];
        const float4* ew4 = (const float4*)(ew + (size_t)e * 16);
        float4 e0 = ew4[0], e1 = ew4[1], e2 = ew4[2], e3 = ew4[3];
        float ewv[16] = { e0.x, e0.y, e0.z, e0.w, e1.x, e1.y, e1.z, e1.w,
                          e2.x, e2.y, e2.z, e2.w, e3.x, e3.y, e3.z, e3.w };

        float f0 = base0 + F[(size_t)u * 256 + c0];   // + f_ni[src]
        float f1 = base1 + F[(size_t)u * 256 + c1];
#pragma unroll
        for (int j = 0; j < 16; j++) {
            f0 = fmaf(ewv[j], Wc0[j], f0);
            f1 = fmaf(ewv[j], Wc1[j], f1);
        }
        // leaky relu (0.2)
        f0 = (f0 > 0.f) ? f0 : 0.2f * f0;
        f1 = (f1 > 0.f) ? f1 : 0.2f * f1;
        float t0 = f0 * a0;
        float t1 = f1 * a1;
        // reduce within 16-lane head groups
#pragma unroll
        for (int o = 8; o >= 1; o >>= 1) {
            t0 += __shfl_xor_sync(0xffffffffu, t0, o);
            t1 += __shfl_xor_sync(0xffffffffu, t1, o);
        }
        float l0 = __shfl_sync(0xffffffffu, t0, 0);
        float l1 = __shfl_sync(0xffffffffu, t0, 16);
        float l2 = __shfl_sync(0xffffffffu, t1, 0);
        float l3 = __shfl_sync(0xffffffffu, t1, 16);

        const float* ftu = F + (size_t)u * 256 + 128;
        float ft0 = ftu[lane];
        float ft1 = ftu[32 + lane];
        float ft2 = ftu[64 + lane];
        float ft3 = ftu[96 + lane];

        // online softmax per head
        float nm, sc, p;
        nm = fmaxf(m0, l0); sc = __expf(m0 - nm); p = __expf(l0 - nm);
        s0 = s0 * sc + p; A0 = fmaf(A0, sc, p * ft0); m0 = nm;
        nm = fmaxf(m1, l1); sc = __expf(m1 - nm); p = __expf(l1 - nm);
        s1 = s1 * sc + p; A1 = fmaf(A1, sc, p * ft1); m1 = nm;
        nm = fmaxf(m2, l2); sc = __expf(m2 - nm); p = __expf(l2 - nm);
        s2 = s2 * sc + p; A2 = fmaf(A2, sc, p * ft2); m2 = nm;
        nm = fmaxf(m3, l3); sc = __expf(m3 - nm); p = __expf(l3 - nm);
        s3 = s3 * sc + p; A3 = fmaf(A3, sc, p * ft3); m3 = nm;
    }

    float o0 = 0.f, o1 = 0.f, o2 = 0.f, o3 = 0.f;
    if (end > beg) {
        o0 = fmaxf(A0 / s0, 0.f);
        o1 = fmaxf(A1 / s1, 0.f);
        o2 = fmaxf(A2 / s2, 0.f);
        o3 = fmaxf(A3 / s3, 0.f);
    }
    float* op = out + (size_t)v * 128;
    op[lane]      = o0;
    op[32 + lane] = o1;
    op[64 + lane] = o2;
    op[96 + lane] = o3;
}

// ---------------- final linear (128 -> 1): one warp per node ----------------
__global__ void lin2_k(const float* __restrict__ h, const float* __restrict__ w,
                       const float* __restrict__ b, float* __restrict__ out, int n) {
    int warpId = (blockIdx.x * blockDim.x + threadIdx.x) >> 5;
    int lane = threadIdx.x & 31;
    if (warpId >= n) return;
    float4 hv = *(const float4*)(h + (size_t)warpId * 128 + lane * 4);
    float4 wv = *(const float4*)(w + lane * 4);
    float acc = hv.x * wv.x + hv.y * wv.y + hv.z * wv.z + hv.w * wv.w;
#pragma unroll
    for (int o = 16; o >= 1; o >>= 1) acc += __shfl_xor_sync(0xffffffffu, acc, o);
    if (lane == 0) out[warpId] = acc + b[0];
}

// ---------------- launch ----------------
extern "C" void kernel_launch(void* const* d_in, const int* in_sizes, int n_in,
                              void* d_out, int out_size) {
    const float* x   = (const float*)d_in[0];
    const float* ew  = (const float*)d_in[1];
    const int*   src = (const int*)d_in[2];
    const int*   dst = (const int*)d_in[3];
    const float* lin1_w = (const float*)d_in[22];
    const float* lin1_b = (const float*)d_in[23];
    const float* lin2_w = (const float*)d_in[24];
    const float* lin2_b = (const float*)d_in[25];
    float* out = (float*)d_out;

    int n = in_sizes[0] / 128;
    int e = in_sizes[2];

    float *pF, *ph, *pW;
    int *pRow, *pCur, *pPerm;
    cudaGetSymbolAddress((void**)&pF, g_F);
    cudaGetSymbolAddress((void**)&ph, g_h);
    cudaGetSymbolAddress((void**)&pW, g_Wcat);
    cudaGetSymbolAddress((void**)&pRow, g_rowptr);
    cudaGetSymbolAddress((void**)&pCur, g_cursor);
    cudaGetSymbolAddress((void**)&pPerm, g_perm);

    // ---- CSR by dst (built once, reused by all 3 layers) ----
    zero_k<<<(n + 255) / 256, 256>>>(pCur, n);
    count_k<<<(e + 255) / 256, 256>>>(dst, pCur, e);
    scan_k<<<1, 1024>>>(pCur, pRow, n);
    copy_k<<<(n + 255) / 256, 256>>>(pRow, pCur, n);
    scatter_k<<<(e + 255) / 256, 256>>>(dst, pCur, pPerm, e);

    dim3 gF((256 + BN - 1) / BN, (n + BM - 1) / BM);
    dim3 gL((128 + BN - 1) / BN, (n + BM - 1) / BM);
    int egatBlocks = (n * 32 + 255) / 256;

    const float* X = x;
    for (int l = 0; l < 3; l++) {
        const float* Wn   = (const float*)d_in[4 + 6 * l + 0];
        const float* Wni  = (const float*)d_in[4 + 6 * l + 1];
        const float* Wnj  = (const float*)d_in[4 + 6 * l + 2];
        const float* Wfij = (const float*)d_in[4 + 6 * l + 3];
        const float* attn = (const float*)d_in[4 + 6 * l + 4];
        const float* bias = (const float*)d_in[4 + 6 * l + 5];

        pack_k<<<(128 * 256 + 255) / 256, 256>>>(Wni, Wnj, Wn, pW);
        sgemm_k<<<gF, 256>>>(X, pW, pF, n, 256, nullptr, 0);
        egat_k<<<egatBlocks, 256>>>(pF, ew, pRow, pPerm, src, Wfij, attn, bias, ph, n);
        X = ph;
    }

    // MLP head: lin1 (relu) into g_F, then lin2 into out
    sgemm_k<<<gL, 256>>>(ph, lin1_w, pF, n, 128, lin1_b, 1);
    lin2_k<<<(n * 32 + 255) / 256, 256>>>(pF, lin2_w, lin2_b, out, n);
}